// round 6
// baseline (speedup 1.0000x reference)
#include <cuda_runtime.h>
#include <cuda_bf16.h>
#include <math.h>

// Problem constants
constexpr int S  = 1024;
constexpr int Mm = 128;
constexpr int D  = 1024;
constexpr int H  = 16;
constexpr int HD = 64;
constexpr int F  = 2048;
constexpr int L  = 8;
constexpr int TOT = S + 2 * Mm;     // 1280
constexpr int KHID = Mm + S;        // 1152

// ---------------- f32 scratch pool ----------------
constexpr size_t OFF_CAT  = 0;                          // 1280*1024
constexpr size_t OFF_Q    = 5242880;                    // 16*1024*64
constexpr size_t OFF_QB   = 6291456;
constexpr size_t OFF_QF   = 6422528;
constexpr size_t OFF_K    = 6553600;                    // 16*1280*64
constexpr size_t OFF_V    = 7864320;
constexpr size_t OFF_KF   = 9175040;
constexpr size_t OFF_VF   = 9306112;
constexpr size_t OFF_TQKV = 9437184;                    // 3*1024*1024
constexpr size_t OFF_TSM  = 12582912;                   // 8*128*1024
constexpr size_t OFF_TG   = 13631488;                   // 1280*2048
constexpr size_t OFF_TU   = 16252928;                   // 1280*2048
constexpr size_t OFF_COS  = 18874368;
constexpr size_t OFF_SIN  = 18956288;
constexpr size_t OFF_XF   = 19038208;                   // 1280*1024 f32
constexpr size_t OFF_YF   = 20348928;
constexpr size_t OFF_AF   = 21659648;
constexpr size_t OFF_GF   = 22970368;                   // 1280*2048 f32
constexpr size_t POOL_SZ  = 25591808;
__device__ __align__(16) float g_pool[POOL_SZ];

// ---------------- bf16 scratch pool ----------------
constexpr size_t BW_DXD   = 0;                   // i-th DxD: hi at i*2097152, lo +1048576
constexpr size_t BW_WG    = 25165824;            // hi, lo +2097152
constexpr size_t BW_WU    = 29360128;
constexpr size_t BW_WD    = 33554432;
constexpr size_t B_XH     = 37748736;            // 1280*1024
constexpr size_t B_XL     = 39059456;
constexpr size_t B_AH     = 40370176;
constexpr size_t B_AL     = 41680896;
constexpr size_t B_YH     = 42991616;
constexpr size_t B_YL     = 44302336;
constexpr size_t B_GH     = 45613056;            // 1280*2048
constexpr size_t B_GL     = 48234496;
constexpr size_t B_MEH    = 50855936;            // 128*1024
constexpr size_t B_MEL    = 50987008;
constexpr size_t BPOOL_SZ = 51118080;
__device__ __align__(16) __nv_bfloat16 g_poolbf[BPOOL_SZ];

// ---------------- rope tables ----------------
__global__ void k_tables(float* cosT, float* sinT) {
    int idx = blockIdx.x * blockDim.x + threadIdx.x;
    if (idx >= 1280 * 64) return;
    int p = idx >> 6;
    int d = idx & 63;
    int i = d & 31;
    double inv = pow(10000.0, -((double)i) / 32.0);
    double ang = (double)p * inv;
    cosT[idx] = (float)cos(ang);
    sinT[idx] = (float)sin(ang);
}

// ---------------- initial residual ----------------
__global__ void k_fillcat(float* cat, const int* __restrict__ ids,
                          const float* __restrict__ embed,
                          const float* __restrict__ beacon,
                          const float* __restrict__ forget) {
    int idx = blockIdx.x * blockDim.x + threadIdx.x;
    if (idx >= TOT * D) return;
    int row = idx >> 10;
    int d = idx & 1023;
    float v;
    if (row < S)            v = embed[(size_t)ids[row] * D + d];
    else if (row < S + Mm)  v = beacon[(size_t)(row - S) * D + d];
    else                    v = forget[(size_t)(row - S - Mm) * D + d];
    cat[idx] = v;
}

// ---------------- gated output ----------------
__global__ void k_outgate(float* __restrict__ out, const float* __restrict__ mem,
                          const float* __restrict__ cat) {
    int idx = blockIdx.x * blockDim.x + threadIdx.x;
    if (idx >= Mm * D) return;
    float bcn = cat[(size_t)S * D + idx];
    float fgt = cat[(size_t)(S + Mm) * D + idx];
    float g = 1.0f / (1.0f + expf(-fgt));
    out[idx] = mem[idx] * g + bcn * (1.0f - g);
}

// ---------------- rmsnorm -> bf16 hi/lo + f32 ----------------
__global__ void k_rms(const float* __restrict__ in, const float* __restrict__ w,
                      __nv_bfloat16* __restrict__ oh, __nv_bfloat16* __restrict__ ol,
                      float* __restrict__ of) {
    int row = blockIdx.x;
    const float* r = in + (size_t)row * D;
    float ss = 0.0f;
    for (int i = threadIdx.x; i < D; i += 256) { float v = r[i]; ss = fmaf(v, v, ss); }
    #pragma unroll
    for (int o = 16; o; o >>= 1) ss += __shfl_xor_sync(0xffffffffu, ss, o);
    __shared__ float wsum[8];
    __shared__ float sc;
    if ((threadIdx.x & 31) == 0) wsum[threadIdx.x >> 5] = ss;
    __syncthreads();
    if (threadIdx.x == 0) {
        float tot = 0.0f;
        #pragma unroll
        for (int i = 0; i < 8; i++) tot += wsum[i];
        sc = rsqrtf(tot / (float)D + 1e-5f);
    }
    __syncthreads();
    float scale = sc;
    size_t base = (size_t)row * D;
    for (int i = threadIdx.x; i < D; i += 256) {
        float v = r[i] * scale * w[i];
        __nv_bfloat16 h = __float2bfloat16(v);
        oh[base + i] = h;
        ol[base + i] = __float2bfloat16(v - __bfloat162float(h));
        of[base + i] = v;
    }
}

// ---------------- weight transpose + hi/lo split ----------------
struct WcEnt { const float* src; __nv_bfloat16* dh; __nv_bfloat16* dl; int K; int N; int blkOff; };
struct WcArgs { WcEnt e[15]; };

__global__ void __launch_bounds__(256) k_wconv(WcArgs wa) {
    __shared__ float ts[32][33];
    int b = blockIdx.x;
    int ei = 0;
    #pragma unroll
    for (int i = 14; i >= 1; i--) if (b >= wa.e[i].blkOff) { ei = i; break; }
    WcEnt E = wa.e[ei];
    int local = b - E.blkOff;
    int ntx = E.N >> 5;
    int tn = (local % ntx) << 5;
    int tk = (local / ntx) << 5;
    int tx = threadIdx.x & 31, ty = threadIdx.x >> 5;
    #pragma unroll
    for (int j = 0; j < 4; j++)
        ts[ty + j * 8][tx] = E.src[(size_t)(tk + ty + j * 8) * E.N + tn + tx];
    __syncthreads();
    #pragma unroll
    for (int j = 0; j < 4; j++) {
        float v = ts[tx][ty + j * 8];
        __nv_bfloat16 h = __float2bfloat16(v);
        size_t o = (size_t)(tn + ty + j * 8) * E.K + tk + tx;
        E.dh[o] = h;
        E.dl[o] = __float2bfloat16(v - __bfloat162float(h));
    }
}

// ---------------- plain f32 -> bf16 hi/lo split ----------------
__global__ void k_split(const float* __restrict__ src, __nv_bfloat16* __restrict__ dh,
                        __nv_bfloat16* __restrict__ dl, int n) {
    int i = blockIdx.x * 256 + threadIdx.x;
    if (i >= n) return;
    float v = src[i];
    __nv_bfloat16 h = __float2bfloat16(v);
    dh[i] = h;
    dl[i] = __float2bfloat16(v - __bfloat162float(h));
}

// =======================================================================
// Hybrid GEMM: per CTA, warps 0-7 do a 128x128 HMMA tile (3-term bf16
// hi/lo split), warps 8-11 concurrently do a 128x96 pure-fp32 FFMA tile
// on different N-columns. Layout per stripe: [128*nH HMMA | 96*nF FFMA].
// =======================================================================
struct GArgs {
    const __nv_bfloat16* Ah[11]; const __nv_bfloat16* Al[11];
    const __nv_bfloat16* Bh[11]; const __nv_bfloat16* Bl[11];
    const float* Af[11]; const float* Bf[11];
    float* C[11];
    int mRows[11];
};

__device__ __forceinline__ void mma16816(float* c, const unsigned* a, const unsigned* b) {
    asm volatile(
        "mma.sync.aligned.m16n8k16.row.col.f32.bf16.bf16.f32 "
        "{%0,%1,%2,%3}, {%4,%5,%6,%7}, {%8,%9}, {%0,%1,%2,%3};"
        : "+f"(c[0]), "+f"(c[1]), "+f"(c[2]), "+f"(c[3])
        : "r"(a[0]), "r"(a[1]), "r"(a[2]), "r"(a[3]), "r"(b[0]), "r"(b[1]));
}
__device__ __forceinline__ void ldsm4(unsigned* r, unsigned addr) {
    asm volatile("ldmatrix.sync.aligned.m8n8.x4.shared.b16 {%0,%1,%2,%3}, [%4];"
                 : "=r"(r[0]), "=r"(r[1]), "=r"(r[2]), "=r"(r[3]) : "r"(addr));
}
__device__ __forceinline__ void cpasync16(unsigned saddr, const void* gptr) {
    asm volatile("cp.async.cg.shared.global [%0], [%1], 16;"
                 :: "r"(saddr), "l"(gptr) : "memory");
}
__device__ __forceinline__ void cp_commit() {
    asm volatile("cp.async.commit_group;" ::: "memory");
}
template<int NN> __device__ __forceinline__ void cp_wait() {
    asm volatile("cp.async.wait_group %0;" :: "n"(NN) : "memory");
}
__device__ __forceinline__ void barH() {   // HMMA group barrier (256 thr)
    asm volatile("bar.sync 1, 256;" ::: "memory");
}
__device__ __forceinline__ void barF() {   // FFMA group barrier (128 thr)
    asm volatile("bar.sync 2, 128;" ::: "memory");
}

constexpr int SMEM_HY = 131072 + 2 * 14848;   // HMMA 2x64KB + FFMA 2x14.5KB

__global__ void __launch_bounds__(384, 1) k_hyb(GArgs ga, int N, int K, int accFlag,
                                                int nH, int nF) {
    extern __shared__ __align__(128) char smraw[];
    const int z = blockIdx.z;
    const int mbase = blockIdx.y << 7;
    if (mbase >= ga.mRows[z]) return;
    const int t = threadIdx.x;

    if (t < 256) {
        // =================== HMMA group (warps 0-7) ===================
        if ((int)blockIdx.x >= nH) return;
        const int nbase = blockIdx.x << 7;
        const __nv_bfloat16* Ah = ga.Ah[z];
        const __nv_bfloat16* Al = ga.Al[z];
        const __nv_bfloat16* Bh = ga.Bh[z];
        const __nv_bfloat16* Bl = ga.Bl[z];
        float* C = ga.C[z];

        const int l = t & 31;
        const int w = t >> 5;
        const int wr = w >> 2;
        const int wc = w & 3;
        const unsigned sb = (unsigned)__cvta_generic_to_shared(smraw);

        auto load_stage = [&](int c, int s) {
            unsigned stg = sb + (unsigned)s * 65536u;
            int k0 = c << 6;
            #pragma unroll
            for (int i = 0; i < 4; i++) {
                int id = t + i * 256;
                int row = id >> 3, kc = id & 7;
                unsigned soff = stg + (unsigned)row * 128u + (unsigned)((kc ^ (row & 7)) << 4);
                size_t ao = (size_t)(mbase + row) * K + k0 + kc * 8;
                size_t bo = (size_t)(nbase + row) * K + k0 + kc * 8;
                cpasync16(soff,          Ah + ao);
                cpasync16(soff + 16384u, Al + ao);
                cpasync16(soff + 32768u, Bh + bo);
                cpasync16(soff + 49152u, Bl + bo);
            }
            cp_commit();
        };

        float acc[4][4][4];
        #pragma unroll
        for (int i = 0; i < 4; i++)
            #pragma unroll
            for (int j = 0; j < 4; j++)
                #pragma unroll
                for (int q = 0; q < 4; q++) acc[i][j][q] = 0.0f;

        const int nc = K >> 6;
        load_stage(0, 0);
        if (nc > 1) load_stage(1, 1);

        for (int c = 0; c < nc; c++) {
            if (c + 1 < nc) cp_wait<1>(); else cp_wait<0>();
            barH();
            unsigned stg = sb + (unsigned)(c & 1) * 65536u;
            #pragma unroll
            for (int ks = 0; ks < 4; ks++) {
                unsigned aH[4][4], aL[4][4], bH[2][4], bL[2][4];
                #pragma unroll
                for (int mt = 0; mt < 4; mt++) {
                    int row = wr * 64 + mt * 16 + (l & 15);
                    int chunk = ks * 2 + (l >> 4);
                    unsigned off = stg + (unsigned)row * 128u + (unsigned)((chunk ^ (row & 7)) << 4);
                    ldsm4(aH[mt], off);
                    ldsm4(aL[mt], off + 16384u);
                }
                #pragma unroll
                for (int p = 0; p < 2; p++) {
                    int nrow = wc * 32 + p * 16 + ((l >> 1) & 8) + (l & 7);
                    int chunk = ks * 2 + ((l >> 3) & 1);
                    unsigned off = stg + 32768u + (unsigned)nrow * 128u +
                                   (unsigned)((chunk ^ (nrow & 7)) << 4);
                    ldsm4(bH[p], off);
                    ldsm4(bL[p], off + 16384u);
                }
                #pragma unroll
                for (int mt = 0; mt < 4; mt++)
                    #pragma unroll
                    for (int j = 0; j < 4; j++) {
                        const unsigned* bh = &bH[j >> 1][(j & 1) * 2];
                        const unsigned* bl = &bL[j >> 1][(j & 1) * 2];
                        mma16816(acc[mt][j], aH[mt], bh);
                        mma16816(acc[mt][j], aH[mt], bl);
                        mma16816(acc[mt][j], aL[mt], bh);
                    }
            }
            barH();
            if (c + 2 < nc) load_stage(c + 2, c & 1);
        }

        int r0 = wr * 64 + (l >> 2);
        int c0 = wc * 32 + (l & 3) * 2;
        #pragma unroll
        for (int mt = 0; mt < 4; mt++) {
            #pragma unroll
            for (int j = 0; j < 4; j++) {
                int row = mbase + r0 + mt * 16;
                int col = nbase + c0 + j * 8;
                float2 v01 = { acc[mt][j][0], acc[mt][j][1] };
                float2 v23 = { acc[mt][j][2], acc[mt][j][3] };
                float* p0 = C + (size_t)row * N + col;
                float* p1 = C + (size_t)(row + 8) * N + col;
                if (accFlag) {
                    float2 o0 = *(const float2*)p0;
                    float2 o1 = *(const float2*)p1;
                    v01.x += o0.x; v01.y += o0.y;
                    v23.x += o1.x; v23.y += o1.y;
                }
                *(float2*)p0 = v01;
                *(float2*)p1 = v23;
            }
        }
    } else {
        // =================== FFMA group (warps 8-11) ===================
        if ((int)blockIdx.x >= nF) return;
        const int tf = t - 256;
        const int fcol = nH * 128 + (int)blockIdx.x * 96;
        const float* Af = ga.Af[z];
        const float* Bf = ga.Bf[z];
        float* C = ga.C[z];
        float* smF = (float*)(smraw + 131072);
        const int tx = tf & 7;          // col group (12 cols)
        const int ty = tf >> 3;         // row group (8 rows)

        float4 av[4], bv[3];
        auto ldF = [&](int kt) {
            int k0 = kt << 4;
            #pragma unroll
            for (int i = 0; i < 4; i++) {
                int idx = tf + i * 128;
                int row = idx >> 2, k4 = (idx & 3) << 2;
                av[i] = *(const float4*)(Af + (size_t)(mbase + row) * K + k0 + k4);
            }
            #pragma unroll
            for (int i = 0; i < 3; i++) {
                int idx = tf + i * 128;
                int krow = idx / 24, cc = (idx % 24) << 2;
                bv[i] = *(const float4*)(Bf + (size_t)(k0 + krow) * N + fcol + cc);
            }
        };
        auto stF = [&](int s) {
            float* ds = smF + s * 3712;
            #pragma unroll
            for (int i = 0; i < 4; i++) {
                int idx = tf + i * 128;
                int row = idx >> 2, k4 = (idx & 3) << 2;
                ds[(k4 + 0) * 132 + row] = av[i].x;
                ds[(k4 + 1) * 132 + row] = av[i].y;
                ds[(k4 + 2) * 132 + row] = av[i].z;
                ds[(k4 + 3) * 132 + row] = av[i].w;
            }
            #pragma unroll
            for (int i = 0; i < 3; i++) {
                int idx = tf + i * 128;
                int krow = idx / 24, cc = (idx % 24) << 2;
                *(float4*)(ds + 2112 + krow * 100 + cc) = bv[i];
            }
        };

        float acc[8][12];
        #pragma unroll
        for (int r = 0; r < 8; r++)
            #pragma unroll
            for (int c = 0; c < 12; c++) acc[r][c] = 0.0f;

        const int nk = K >> 4;
        ldF(0);
        stF(0);
        barF();

        for (int kt = 0; kt < nk; kt++) {
            bool more = (kt + 1 < nk);
            if (more) ldF(kt + 1);
            const float* st = smF + (kt & 1) * 3712;
            #pragma unroll 4
            for (int k = 0; k < 16; k++) {
                const float* ar = st + k * 132 + ty * 8;
                float4 a0 = *(const float4*)ar;
                float4 a1 = *(const float4*)(ar + 4);
                const float* br = st + 2112 + k * 100 + tx * 12;
                float4 b0 = *(const float4*)br;
                float4 b1 = *(const float4*)(br + 4);
                float4 b2 = *(const float4*)(br + 8);
                float a8[8] = {a0.x, a0.y, a0.z, a0.w, a1.x, a1.y, a1.z, a1.w};
                float b12[12] = {b0.x, b0.y, b0.z, b0.w, b1.x, b1.y, b1.z, b1.w,
                                 b2.x, b2.y, b2.z, b2.w};
                #pragma unroll
                for (int r = 0; r < 8; r++)
                    #pragma unroll
                    for (int c = 0; c < 12; c++)
                        acc[r][c] = fmaf(a8[r], b12[c], acc[r][c]);
            }
            if (more) stF((kt + 1) & 1);
            barF();
        }

        #pragma unroll
        for (int r = 0; r < 8; r++) {
            int row = mbase + ty * 8 + r;
            float* cp = C + (size_t)row * N + fcol + tx * 12;
            #pragma unroll
            for (int q = 0; q < 3; q++) {
                float4 v = make_float4(acc[r][q * 4 + 0], acc[r][q * 4 + 1],
                                       acc[r][q * 4 + 2], acc[r][q * 4 + 3]);
                if (accFlag) {
                    float4 o = *(const float4*)(cp + q * 4);
                    v.x += o.x; v.y += o.y; v.z += o.z; v.w += o.w;
                }
                *(float4*)(cp + q * 4) = v;
            }
        }
    }
}

// ---------------- rope + head-major reshape ----------------
struct RsOne {
    const float* src;
    float*       dst;
    int rows;
    int dstStride;
    int dstOff;
    int posBase;
};
struct RsArgs { RsOne e[11]; };

__global__ void k_reshape(RsArgs ra, const float* __restrict__ cosT,
                          const float* __restrict__ sinT) {
    RsOne a = ra.e[blockIdx.y];
    int idx = blockIdx.x * 256 + threadIdx.x;
    if (idx >= a.rows * 1024) return;
    int row = idx >> 10;
    int n = idx & 1023;
    int h = n >> 6;
    int d = n & 63;
    float v = a.src[idx];
    float o;
    if (a.posBase >= 0) {
        int pos = a.posBase + row;
        float partner = (d < 32)
            ? -a.src[(size_t)row * 1024 + h * 64 + d + 32]
            :  a.src[(size_t)row * 1024 + h * 64 + d - 32];
        o = v * cosT[pos * 64 + d] + partner * sinT[pos * 64 + d];
    } else {
        o = v;
    }
    a.dst[((size_t)h * a.dstStride + a.dstOff + row) * 64 + d] = o;
}

// ---------------- flash-style attention -> bf16 hi/lo + f32 out ----------------
__global__ void __launch_bounds__(128) k_attn(
    const float* __restrict__ Q, int nq,
    const float* __restrict__ K1, const float* __restrict__ V1, int len1, int hs1,
    const float* __restrict__ K2, const float* __restrict__ V2, int len2, int hs2,
    int P, __nv_bfloat16* __restrict__ OutH, __nv_bfloat16* __restrict__ OutL,
    float* __restrict__ OutF)
{
    constexpr int TQ = 32, TK = 32;
    int h  = blockIdx.y;
    int qb = blockIdx.x * TQ;
    int t  = threadIdx.x;
    int r  = t >> 2;
    int c4 = t & 3;
    int d0 = c4 * 16;

    __shared__ __align__(16) float Ks[TK][64];
    __shared__ __align__(16) float Vs[TK][64];

    const float* Qh = Q + (size_t)h * nq * 64;

    float qreg[16];
    #pragma unroll
    for (int i = 0; i < 16; i += 4) {
        float4 v = *(const float4*)(Qh + (size_t)(qb + r) * 64 + d0 + i);
        qreg[i + 0] = v.x * 0.125f;
        qreg[i + 1] = v.y * 0.125f;
        qreg[i + 2] = v.z * 0.125f;
        qreg[i + 3] = v.w * 0.125f;
    }

    float m = -3.0e38f, lsum = 0.0f;
    float O[16];
    #pragma unroll
    for (int i = 0; i < 16; i++) O[i] = 0.0f;

    int total = len1 + len2;
    int eff = min(total, P + qb + TQ);
    int ntk = (eff + TK - 1) / TK;
    int qi = qb + r;

    for (int kt = 0; kt < ntk; kt++) {
        int j = kt * TK + r;
        const float *kp, *vp;
        if (j < len1) {
            kp = K1 + (size_t)h * hs1 + (size_t)j * 64;
            vp = V1 + (size_t)h * hs1 + (size_t)j * 64;
        } else {
            kp = K2 + (size_t)h * hs2 + (size_t)(j - len1) * 64;
            vp = V2 + (size_t)h * hs2 + (size_t)(j - len1) * 64;
        }
        __syncthreads();
        #pragma unroll
        for (int i = 0; i < 16; i += 4) {
            *(float4*)(&Ks[r][d0 + i]) = *(const float4*)(kp + d0 + i);
            *(float4*)(&Vs[r][d0 + i]) = *(const float4*)(vp + d0 + i);
        }
        __syncthreads();

        float s[TK];
        #pragma unroll
        for (int k = 0; k < TK; k++) {
            const float4* kp4 = (const float4*)(&Ks[k][d0]);
            float a = 0.0f;
            #pragma unroll
            for (int i4 = 0; i4 < 4; i4++) {
                float4 kv = kp4[i4];
                a = fmaf(qreg[i4 * 4 + 0], kv.x, a);
                a = fmaf(qreg[i4 * 4 + 1], kv.y, a);
                a = fmaf(qreg[i4 * 4 + 2], kv.z, a);
                a = fmaf(qreg[i4 * 4 + 3], kv.w, a);
            }
            s[k] = a;
        }
        #pragma unroll
        for (int k = 0; k < TK; k++) {
            s[k] += __shfl_xor_sync(0xffffffffu, s[k], 1);
            s[k] += __shfl_xor_sync(0xffffffffu, s[k], 2);
        }
        int jg0 = kt * TK;
        #pragma unroll
        for (int k = 0; k < TK; k++) {
            int jg = jg0 + k;
            bool vis = (jg < P) || (jg - P <= qi);
            if (!vis) s[k] = -3.0e38f;
        }
        float tmax = s[0];
        #pragma unroll
        for (int k = 1; k < TK; k++) tmax = fmaxf(tmax, s[k]);
        float nm = fmaxf(m, tmax);
        float corr = __expf(m - nm);
        lsum *= corr;
        #pragma unroll
        for (int i = 0; i < 16; i++) O[i] *= corr;
        #pragma unroll
        for (int k = 0; k < TK; k++) {
            float p = __expf(s[k] - nm);
            lsum += p;
            const float4* vp4 = (const float4*)(&Vs[k][d0]);
            #pragma unroll
            for (int i4 = 0; i4 < 4; i4++) {
                float4 vv = vp4[i4];
                O[i4 * 4 + 0] = fmaf(p, vv.x, O[i4 * 4 + 0]);
                O[i4 * 4 + 1] = fmaf(p, vv.y, O[i4 * 4 + 1]);
                O[i4 * 4 + 2] = fmaf(p, vv.z, O[i4 * 4 + 2]);
                O[i4 * 4 + 3] = fmaf(p, vv.w, O[i4 * 4 + 3]);
            }
        }
        m = nm;
    }

    float inv = 1.0f / lsum;
    size_t base = (size_t)(qb + r) * 1024 + h * 64 + d0;
    #pragma unroll
    for (int i = 0; i < 16; i++) {
        float v = O[i] * inv;
        __nv_bfloat16 hh = __float2bfloat16(v);
        OutH[base + i] = hh;
        OutL[base + i] = __float2bfloat16(v - __bfloat162float(hh));
        OutF[base + i] = v;
    }
}

// ---------------- MLP activation -> bf16 hi/lo + f32 ----------------
__global__ void k_silu(const float* __restrict__ g, const float* __restrict__ u,
                       __nv_bfloat16* __restrict__ oh, __nv_bfloat16* __restrict__ ol,
                       float* __restrict__ of) {
    int idx = blockIdx.x * blockDim.x + threadIdx.x;
    if (idx >= TOT * F) return;
    float x = g[idx];
    float s = x / (1.0f + expf(-x));
    float v = s * u[idx];
    __nv_bfloat16 h = __float2bfloat16(v);
    oh[idx] = h;
    ol[idx] = __float2bfloat16(v - __bfloat162float(h));
    of[idx] = v;
}

// ---------------- host driver ----------------
extern "C" void kernel_launch(void* const* d_in, const int* in_sizes, int n_in,
                              void* d_out, int out_size) {
    (void)in_sizes; (void)n_in; (void)out_size;

    const int*   ids    = (const int*)  d_in[0];
    const float* memory = (const float*)d_in[1];
    const float* beacon = (const float*)d_in[2];
    const float* forget = (const float*)d_in[3];
    const float* embed  = (const float*)d_in[4];
    const float* ln1    = (const float*)d_in[5];
    const float* ln2    = (const float*)d_in[6];
    const float* Wsrc[12] = {
        (const float*)d_in[7],  (const float*)d_in[8],  (const float*)d_in[9],
        (const float*)d_in[10], (const float*)d_in[11], (const float*)d_in[12],
        (const float*)d_in[13], (const float*)d_in[14], (const float*)d_in[15],
        (const float*)d_in[16], (const float*)d_in[17], (const float*)d_in[18]
    }; // Wq Wk Wv Wo mWk mWv bWq bWk bWv fWq fWk fWv
    const float* Wg = (const float*)d_in[19];
    const float* Wu = (const float*)d_in[20];
    const float* Wd = (const float*)d_in[21];
    float* out = (float*)d_out;

    float* pool = nullptr;
    cudaGetSymbolAddress((void**)&pool, g_pool);
    __nv_bfloat16* bp = nullptr;
    cudaGetSymbolAddress((void**)&bp, g_poolbf);

    float* cat  = pool + OFF_CAT;
    float* qh_f = pool + OFF_Q;
    float* qbuf_b = pool + OFF_QB;
    float* qbuf_f = pool + OFF_QF;
    float* kbuf = pool + OFF_K;
    float* vbuf = pool + OFF_V;
    float* kf   = pool + OFF_KF;
    float* vf   = pool + OFF_VF;
    float* tqkv = pool + OFF_TQKV;
    float* tsm  = pool + OFF_TSM;
    float* tg   = pool + OFF_TG;
    float* tu   = pool + OFF_TU;
    float* cosT = pool + OFF_COS;
    float* sinT = pool + OFF_SIN;
    float* xf   = pool + OFF_XF;
    float* yf   = pool + OFF_YF;
    float* af   = pool + OFF_AF;
    float* gf   = pool + OFF_GF;

    __nv_bfloat16* xh = bp + B_XH;  __nv_bfloat16* xl = bp + B_XL;
    __nv_bfloat16* ah = bp + B_AH;  __nv_bfloat16* al = bp + B_AL;
    __nv_bfloat16* yh = bp + B_YH;  __nv_bfloat16* yl = bp + B_YL;
    __nv_bfloat16* gh = bp + B_GH;  __nv_bfloat16* gl = bp + B_GL;
    __nv_bfloat16* meh = bp + B_MEH; __nv_bfloat16* mel = bp + B_MEL;

    cudaFuncSetAttribute(k_hyb, cudaFuncAttributeMaxDynamicSharedMemorySize, SMEM_HY);

    k_tables<<<(1280 * 64 + 255) / 256, 256>>>(cosT, sinT);
    k_fillcat<<<(TOT * D + 255) / 256, 256>>>(cat, ids, embed, beacon, forget);

    const size_t WDD = (size_t)D * D;
    const size_t WDF = (size_t)D * F;
    const size_t WFD = (size_t)F * D;
    const size_t MDsz = (size_t)Mm * D;

    __nv_bfloat16* wtH[15]; __nv_bfloat16* wtL[15];
    for (int i = 0; i < 12; i++) {
        wtH[i] = bp + BW_DXD + (size_t)i * 2097152;
        wtL[i] = wtH[i] + 1048576;
    }
    wtH[12] = bp + BW_WG; wtL[12] = wtH[12] + 2097152;
    wtH[13] = bp + BW_WU; wtL[13] = wtH[13] + 2097152;
    wtH[14] = bp + BW_WD; wtL[14] = wtH[14] + 2097152;

    for (int l = 0; l < L; l++) {
        const float* mem_l = memory + (size_t)l * MDsz;

        // per-layer weight conversion (transpose to [N][K] + hi/lo split)
        {
            WcArgs wa;
            int off = 0;
            for (int i = 0; i < 12; i++) {
                wa.e[i] = { Wsrc[i] + (size_t)l * WDD, wtH[i], wtL[i], D, D, off };
                off += (D / 32) * (D / 32);
            }
            wa.e[12] = { Wg + (size_t)l * WDF, wtH[12], wtL[12], D, F, off }; off += (D/32)*(F/32);
            wa.e[13] = { Wu + (size_t)l * WDF, wtH[13], wtL[13], D, F, off }; off += (D/32)*(F/32);
            wa.e[14] = { Wd + (size_t)l * WFD, wtH[14], wtL[14], F, D, off }; off += (F/32)*(D/32);
            k_wconv<<<off, 256>>>(wa);
        }
        k_split<<<(Mm * D + 255) / 256, 256>>>(mem_l, meh, mel, Mm * D);

        k_outgate<<<(Mm * D + 255) / 256, 256>>>(out + (size_t)l * MDsz, mem_l, cat);
        k_rms<<<TOT, 256>>>(cat, ln1 + (size_t)l * D, xh, xl, xf);

        // merged: hidden QKV (z0-2, M=1024) + eight 128-row projections (z3-10)
        // N=1024 -> 5 HMMA tiles (640 cols) + 4 FFMA tiles (384 cols)
        {
            GArgs ga = {};
            for (int z = 0; z < 3; z++) {
                ga.Ah[z] = xh; ga.Al[z] = xl;
                ga.Bh[z] = wtH[z]; ga.Bl[z] = wtL[z];
                ga.Af[z] = xf; ga.Bf[z] = Wsrc[z] + (size_t)l * WDD;
                ga.C[z] = tqkv + (size_t)z * 1048576;
                ga.mRows[z] = S;
            }
            const __nv_bfloat16* bxh = xh + (size_t)S * D;
            const __nv_bfloat16* bxl = xl + (size_t)S * D;
            const __nv_bfloat16* fxh = xh + (size_t)(S + Mm) * D;
            const __nv_bfloat16* fxl = xl + (size_t)(S + Mm) * D;
            const float* bxf = xf + (size_t)S * D;
            const float* fxf = xf + (size_t)(S + Mm) * D;
            const __nv_bfloat16* sAh[8] = { meh, meh, bxh, bxh, bxh, fxh, fxh, fxh };
            const __nv_bfloat16* sAl[8] = { mel, mel, bxl, bxl, bxl, fxl, fxl, fxl };
            const float* sAf[8] = { mem_l, mem_l, bxf, bxf, bxf, fxf, fxf, fxf };
            int wmap[8] = {4, 5, 6, 7, 8, 9, 10, 11};
            for (int z = 0; z < 8; z++) {
                ga.Ah[3 + z] = sAh[z]; ga.Al[3 + z] = sAl[z];
                ga.Bh[3 + z] = wtH[wmap[z]]; ga.Bl[3 + z] = wtL[wmap[z]];
                ga.Af[3 + z] = sAf[z];
                ga.Bf[3 + z] = Wsrc[wmap[z]] + (size_t)l * WDD;
                ga.C[3 + z] = tsm + (size_t)z * 131072;
                ga.mRows[3 + z] = Mm;
            }
            k_hyb<<<dim3(5, 8, 11), 384, SMEM_HY>>>(ga, D, D, 0, 5, 4);
        }
        // rope + reshape
        {
            RsArgs ra;
            ra.e[0]  = { tqkv,            qh_f,   S,  1024, 0,    Mm };
            ra.e[1]  = { tqkv + 1048576,  kbuf,   S,  1280, 128,  Mm };
            ra.e[2]  = { tqkv + 2097152,  vbuf,   S,  1280, 128,  -1 };
            ra.e[3]  = { tsm,             kbuf,   Mm, 1280, 0,    0  };
            ra.e[4]  = { tsm + 131072,    vbuf,   Mm, 1280, 0,    -1 };
            ra.e[5]  = { tsm + 262144,    qbuf_b, Mm, 128,  0,    KHID };
            ra.e[6]  = { tsm + 393216,    kbuf,   Mm, 1280, KHID, KHID };
            ra.e[7]  = { tsm + 524288,    vbuf,   Mm, 1280, KHID, -1 };
            ra.e[8]  = { tsm + 655360,    qbuf_f, Mm, 128,  0,    KHID };
            ra.e[9]  = { tsm + 786432,    kf,     Mm, 128,  0,    KHID };
            ra.e[10] = { tsm + 917504,    vf,     Mm, 128,  0,    -1 };
            k_reshape<<<dim3(4096, 11), 256>>>(ra, cosT, sinT);
        }
        // attention
        k_attn<<<dim3(S / 32, H), 128>>>(qh_f, S,
                                         kbuf, vbuf, KHID, 1280 * 64,
                                         kf, vf, 0, 128 * 64,
                                         Mm, ah, al, af);
        k_attn<<<dim3(Mm / 32, H), 128>>>(qbuf_b, Mm,
                                          kbuf, vbuf, TOT, 1280 * 64,
                                          kf, vf, 0, 128 * 64,
                                          KHID, ah + (size_t)S * D, al + (size_t)S * D,
                                          af + (size_t)S * D);
        k_attn<<<dim3(Mm / 32, H), 128>>>(qbuf_f, Mm,
                                          kbuf, vbuf, KHID, 1280 * 64,
                                          kf, vf, Mm, 128 * 64,
                                          KHID, ah + (size_t)KHID * D, al + (size_t)KHID * D,
                                          af + (size_t)KHID * D);
        // Wo (+residual): M=1280, N=1024, K=1024
        {
            GArgs ga = {};
            ga.Ah[0] = ah; ga.Al[0] = al;
            ga.Bh[0] = wtH[3]; ga.Bl[0] = wtL[3];
            ga.Af[0] = af; ga.Bf[0] = Wsrc[3] + (size_t)l * WDD;
            ga.C[0] = cat;
            ga.mRows[0] = TOT;
            k_hyb<<<dim3(5, 10, 1), 384, SMEM_HY>>>(ga, D, D, 1, 5, 4);
        }
        k_rms<<<TOT, 256>>>(cat, ln2 + (size_t)l * D, yh, yl, yf);
        // MLP gate & up: M=1280, N=2048, K=1024 -> 10 H tiles + 8 F tiles
        {
            GArgs ga = {};
            ga.Ah[0] = yh; ga.Al[0] = yl; ga.Ah[1] = yh; ga.Al[1] = yl;
            ga.Bh[0] = wtH[12]; ga.Bl[0] = wtL[12];
            ga.Bh[1] = wtH[13]; ga.Bl[1] = wtL[13];
            ga.Af[0] = yf; ga.Af[1] = yf;
            ga.Bf[0] = Wg + (size_t)l * WDF;
            ga.Bf[1] = Wu + (size_t)l * WDF;
            ga.C[0] = tg; ga.C[1] = tu;
            ga.mRows[0] = TOT; ga.mRows[1] = TOT;
            k_hyb<<<dim3(10, 10, 2), 384, SMEM_HY>>>(ga, F, D, 0, 10, 8);
        }
        k_silu<<<(TOT * F + 255) / 256, 256>>>(tg, tu, gh, gl, gf);
        // down (+residual): M=1280, N=1024, K=2048
        {
            GArgs ga = {};
            ga.Ah[0] = gh; ga.Al[0] = gl;
            ga.Bh[0] = wtH[14]; ga.Bl[0] = wtL[14];
            ga.Af[0] = gf; ga.Bf[0] = Wd + (size_t)l * WFD;
            ga.C[0] = cat;
            ga.mRows[0] = TOT;
            k_hyb<<<dim3(5, 10, 1), 384, SMEM_HY>>>(ga, D, F, 1, 5, 4);
        }
    }
}

// round 7
// speedup vs baseline: 1.5141x; 1.5141x over previous
#include <cuda_runtime.h>
#include <cuda_fp16.h>
#include <math.h>

// Problem constants
constexpr int S  = 1024;
constexpr int Mm = 128;
constexpr int D  = 1024;
constexpr int H  = 16;
constexpr int HD = 64;
constexpr int F  = 2048;
constexpr int L  = 8;
constexpr int TOT = S + 2 * Mm;     // 1280
constexpr int KHID = Mm + S;        // 1152

// ---------------- f32 scratch pool ----------------
constexpr size_t OFF_CAT  = 0;                          // 1280*1024
constexpr size_t OFF_Q    = 5242880;                    // 16*1024*64
constexpr size_t OFF_QB   = 6291456;
constexpr size_t OFF_QF   = 6422528;
constexpr size_t OFF_K    = 6553600;                    // 16*1280*64
constexpr size_t OFF_V    = 7864320;
constexpr size_t OFF_KF   = 9175040;
constexpr size_t OFF_VF   = 9306112;
constexpr size_t OFF_TQKV = 9437184;                    // 3*1024*1024
constexpr size_t OFF_TSM  = 12582912;                   // 8*128*1024
constexpr size_t OFF_TG   = 13631488;                   // 1280*2048
constexpr size_t OFF_TU   = 16252928;                   // 1280*2048
constexpr size_t OFF_COS  = 18874368;
constexpr size_t OFF_SIN  = 18956288;
constexpr size_t POOL_SZ  = 19038208;
__device__ __align__(16) float g_pool[POOL_SZ];

// ---------------- fp16 scratch pool ----------------
constexpr size_t BW_DXD   = 0;                   // i-th DxD weight hi: i*1048576
constexpr size_t BW_WG    = 12582912;            // 2*1048576 each
constexpr size_t BW_WU    = 14680064;
constexpr size_t BW_WD    = 16777216;
constexpr size_t B_XH     = 18874368;            // 1280*1024
constexpr size_t B_XL     = 20185088;
constexpr size_t B_AH     = 21495808;
constexpr size_t B_AL     = 22806528;
constexpr size_t B_YH     = 24117248;
constexpr size_t B_YL     = 25427968;
constexpr size_t B_GH     = 26738688;            // 1280*2048
constexpr size_t B_GL     = 29360128;
constexpr size_t B_MEH    = 31981568;            // 128*1024
constexpr size_t B_MEL    = 32112640;
constexpr size_t BPOOL_SZ = 32243712;
__device__ __align__(16) __half g_poolhf[BPOOL_SZ];

// ---------------- rope tables ----------------
__global__ void k_tables(float* cosT, float* sinT) {
    int idx = blockIdx.x * blockDim.x + threadIdx.x;
    if (idx >= 1280 * 64) return;
    int p = idx >> 6;
    int d = idx & 63;
    int i = d & 31;
    double inv = pow(10000.0, -((double)i) / 32.0);
    double ang = (double)p * inv;
    cosT[idx] = (float)cos(ang);
    sinT[idx] = (float)sin(ang);
}

// ---------------- initial residual ----------------
__global__ void k_fillcat(float* cat, const int* __restrict__ ids,
                          const float* __restrict__ embed,
                          const float* __restrict__ beacon,
                          const float* __restrict__ forget) {
    int idx = blockIdx.x * blockDim.x + threadIdx.x;
    if (idx >= TOT * D) return;
    int row = idx >> 10;
    int d = idx & 1023;
    float v;
    if (row < S)            v = embed[(size_t)ids[row] * D + d];
    else if (row < S + Mm)  v = beacon[(size_t)(row - S) * D + d];
    else                    v = forget[(size_t)(row - S - Mm) * D + d];
    cat[idx] = v;
}

// ---------------- gated output ----------------
__global__ void k_outgate(float* __restrict__ out, const float* __restrict__ mem,
                          const float* __restrict__ cat) {
    int idx = blockIdx.x * blockDim.x + threadIdx.x;
    if (idx >= Mm * D) return;
    float bcn = cat[(size_t)S * D + idx];
    float fgt = cat[(size_t)(S + Mm) * D + idx];
    float g = 1.0f / (1.0f + expf(-fgt));
    out[idx] = mem[idx] * g + bcn * (1.0f - g);
}

// ---------------- rmsnorm -> fp16 hi/lo ----------------
__global__ void k_rms(const float* __restrict__ in, const float* __restrict__ w,
                      __half* __restrict__ oh, __half* __restrict__ ol) {
    int row = blockIdx.x;
    const float* r = in + (size_t)row * D;
    float ss = 0.0f;
    for (int i = threadIdx.x; i < D; i += 256) { float v = r[i]; ss = fmaf(v, v, ss); }
    #pragma unroll
    for (int o = 16; o; o >>= 1) ss += __shfl_xor_sync(0xffffffffu, ss, o);
    __shared__ float wsum[8];
    __shared__ float sc;
    if ((threadIdx.x & 31) == 0) wsum[threadIdx.x >> 5] = ss;
    __syncthreads();
    if (threadIdx.x == 0) {
        float tot = 0.0f;
        #pragma unroll
        for (int i = 0; i < 8; i++) tot += wsum[i];
        sc = rsqrtf(tot / (float)D + 1e-5f);
    }
    __syncthreads();
    float scale = sc;
    size_t base = (size_t)row * D;
    for (int i = threadIdx.x; i < D; i += 256) {
        float v = r[i] * scale * w[i];
        __half h = __float2half_rn(v);
        oh[base + i] = h;
        ol[base + i] = __float2half_rn(v - __half2float(h));
    }
}

// ---------------- weight transpose -> fp16 (hi only) ----------------
struct WcEnt { const float* src; __half* dh; int K; int N; int blkOff; };
struct WcArgs { WcEnt e[15]; };

__global__ void __launch_bounds__(256) k_wconv(WcArgs wa) {
    __shared__ float ts[32][33];
    int b = blockIdx.x;
    int ei = 0;
    #pragma unroll
    for (int i = 14; i >= 1; i--) if (b >= wa.e[i].blkOff) { ei = i; break; }
    WcEnt E = wa.e[ei];
    int local = b - E.blkOff;
    int ntx = E.N >> 5;
    int tn = (local % ntx) << 5;
    int tk = (local / ntx) << 5;
    int tx = threadIdx.x & 31, ty = threadIdx.x >> 5;
    #pragma unroll
    for (int j = 0; j < 4; j++)
        ts[ty + j * 8][tx] = E.src[(size_t)(tk + ty + j * 8) * E.N + tn + tx];
    __syncthreads();
    #pragma unroll
    for (int j = 0; j < 4; j++) {
        float v = ts[tx][ty + j * 8];
        E.dh[(size_t)(tn + ty + j * 8) * E.K + tk + tx] = __float2half_rn(v);
    }
}

// ---------------- plain f32 -> fp16 hi/lo split ----------------
__global__ void k_split(const float* __restrict__ src, __half* __restrict__ dh,
                        __half* __restrict__ dl, int n) {
    int i = blockIdx.x * 256 + threadIdx.x;
    if (i >= n) return;
    float v = src[i];
    __half h = __float2half_rn(v);
    dh[i] = h;
    dl[i] = __float2half_rn(v - __half2float(h));
}

// =======================================================================
// HMMA GEMM, 2-term fp16 split: C = Ah@Bh^T + Al@Bh^T (+C).
// A:[M][K] fp16 hi/lo, B:[N][K] fp16 (pre-transposed, single rounding).
// CTA tile 128x128, BK=64, 2-stage cp.async pipeline, 8 warps, 2 CTA/SM.
// smem per stage: Ah 16K | Al 16K | Bh 16K = 48KB; 2 stages = 96KB.
// =======================================================================
struct GArgs {
    const __half* Ah[11]; const __half* Al[11];
    const __half* Bh[11];
    float* C[11];
    int mRows[11];
};

__device__ __forceinline__ void mma16816(float* c, const unsigned* a, const unsigned* b) {
    asm volatile(
        "mma.sync.aligned.m16n8k16.row.col.f32.f16.f16.f32 "
        "{%0,%1,%2,%3}, {%4,%5,%6,%7}, {%8,%9}, {%0,%1,%2,%3};"
        : "+f"(c[0]), "+f"(c[1]), "+f"(c[2]), "+f"(c[3])
        : "r"(a[0]), "r"(a[1]), "r"(a[2]), "r"(a[3]), "r"(b[0]), "r"(b[1]));
}
__device__ __forceinline__ void ldsm4(unsigned* r, unsigned addr) {
    asm volatile("ldmatrix.sync.aligned.m8n8.x4.shared.b16 {%0,%1,%2,%3}, [%4];"
                 : "=r"(r[0]), "=r"(r[1]), "=r"(r[2]), "=r"(r[3]) : "r"(addr));
}
__device__ __forceinline__ void cpasync16(unsigned saddr, const void* gptr) {
    asm volatile("cp.async.cg.shared.global [%0], [%1], 16;"
                 :: "r"(saddr), "l"(gptr) : "memory");
}
__device__ __forceinline__ void cp_commit() {
    asm volatile("cp.async.commit_group;" ::: "memory");
}
template<int NN> __device__ __forceinline__ void cp_wait() {
    asm volatile("cp.async.wait_group %0;" :: "n"(NN) : "memory");
}

constexpr int SMEM_HM = 98304;

__global__ void __launch_bounds__(256, 2) k_hmma(GArgs ga, int N, int K, int accFlag) {
    extern __shared__ __align__(128) char smraw[];
    const int z = blockIdx.z;
    const int mbase = blockIdx.y << 7;
    if (mbase >= ga.mRows[z]) return;
    const int nbase = blockIdx.x << 7;

    const __half* Ah = ga.Ah[z];
    const __half* Al = ga.Al[z];
    const __half* Bh = ga.Bh[z];
    float* C = ga.C[z];

    const int t = threadIdx.x;
    const int l = t & 31;
    const int w = t >> 5;
    const int wr = w >> 2;          // 0..1 -> 64 M rows
    const int wc = w & 3;           // 0..3 -> 32 N cols
    const unsigned sb = (unsigned)__cvta_generic_to_shared(smraw);

    auto load_stage = [&](int c, int s) {
        unsigned stg = sb + (unsigned)s * 49152u;
        int k0 = c << 6;
        #pragma unroll
        for (int i = 0; i < 4; i++) {
            int id = t + i * 256;
            int row = id >> 3, kc = id & 7;
            unsigned soff = stg + (unsigned)row * 128u + (unsigned)((kc ^ (row & 7)) << 4);
            size_t ao = (size_t)(mbase + row) * K + k0 + kc * 8;
            size_t bo = (size_t)(nbase + row) * K + k0 + kc * 8;
            cpasync16(soff,          Ah + ao);
            cpasync16(soff + 16384u, Al + ao);
            cpasync16(soff + 32768u, Bh + bo);
        }
        cp_commit();
    };

    float acc[4][4][4];
    #pragma unroll
    for (int i = 0; i < 4; i++)
        #pragma unroll
        for (int j = 0; j < 4; j++)
            #pragma unroll
            for (int q = 0; q < 4; q++) acc[i][j][q] = 0.0f;

    const int nc = K >> 6;
    load_stage(0, 0);
    if (nc > 1) load_stage(1, 1);

    for (int c = 0; c < nc; c++) {
        if (c + 1 < nc) cp_wait<1>(); else cp_wait<0>();
        __syncthreads();
        unsigned stg = sb + (unsigned)(c & 1) * 49152u;
        #pragma unroll
        for (int ks = 0; ks < 4; ks++) {
            unsigned aH[4][4], aL[4][4], bH[2][4];
            #pragma unroll
            for (int mt = 0; mt < 4; mt++) {
                int row = wr * 64 + mt * 16 + (l & 15);
                int chunk = ks * 2 + (l >> 4);
                unsigned off = stg + (unsigned)row * 128u + (unsigned)((chunk ^ (row & 7)) << 4);
                ldsm4(aH[mt], off);
                ldsm4(aL[mt], off + 16384u);
            }
            #pragma unroll
            for (int p = 0; p < 2; p++) {
                int nrow = wc * 32 + p * 16 + ((l >> 1) & 8) + (l & 7);
                int chunk = ks * 2 + ((l >> 3) & 1);
                unsigned off = stg + 32768u + (unsigned)nrow * 128u +
                               (unsigned)((chunk ^ (nrow & 7)) << 4);
                ldsm4(bH[p], off);
            }
            #pragma unroll
            for (int mt = 0; mt < 4; mt++)
                #pragma unroll
                for (int j = 0; j < 4; j++) {
                    const unsigned* bh = &bH[j >> 1][(j & 1) * 2];
                    mma16816(acc[mt][j], aH[mt], bh);
                    mma16816(acc[mt][j], aL[mt], bh);
                }
        }
        __syncthreads();
        if (c + 2 < nc) load_stage(c + 2, c & 1);
    }

    // epilogue
    int r0 = wr * 64 + (l >> 2);
    int c0 = wc * 32 + (l & 3) * 2;
    #pragma unroll
    for (int mt = 0; mt < 4; mt++) {
        #pragma unroll
        for (int j = 0; j < 4; j++) {
            int row = mbase + r0 + mt * 16;
            int col = nbase + c0 + j * 8;
            float2 v01 = { acc[mt][j][0], acc[mt][j][1] };
            float2 v23 = { acc[mt][j][2], acc[mt][j][3] };
            float* p0 = C + (size_t)row * N + col;
            float* p1 = C + (size_t)(row + 8) * N + col;
            if (accFlag) {
                float2 o0 = *(const float2*)p0;
                float2 o1 = *(const float2*)p1;
                v01.x += o0.x; v01.y += o0.y;
                v23.x += o1.x; v23.y += o1.y;
            }
            *(float2*)p0 = v01;
            *(float2*)p1 = v23;
        }
    }
}

// ---------------- rope + head-major reshape ----------------
struct RsOne {
    const float* src;
    float*       dst;
    int rows;
    int dstStride;
    int dstOff;
    int posBase;
};
struct RsArgs { RsOne e[11]; };

__global__ void k_reshape(RsArgs ra, const float* __restrict__ cosT,
                          const float* __restrict__ sinT) {
    RsOne a = ra.e[blockIdx.y];
    int idx = blockIdx.x * 256 + threadIdx.x;
    if (idx >= a.rows * 1024) return;
    int row = idx >> 10;
    int n = idx & 1023;
    int h = n >> 6;
    int d = n & 63;
    float v = a.src[idx];
    float o;
    if (a.posBase >= 0) {
        int pos = a.posBase + row;
        float partner = (d < 32)
            ? -a.src[(size_t)row * 1024 + h * 64 + d + 32]
            :  a.src[(size_t)row * 1024 + h * 64 + d - 32];
        o = v * cosT[pos * 64 + d] + partner * sinT[pos * 64 + d];
    } else {
        o = v;
    }
    a.dst[((size_t)h * a.dstStride + a.dstOff + row) * 64 + d] = o;
}

// ---------------- flash-style attention -> fp16 hi/lo out ----------------
__global__ void __launch_bounds__(128) k_attn(
    const float* __restrict__ Q, int nq,
    const float* __restrict__ K1, const float* __restrict__ V1, int len1, int hs1,
    const float* __restrict__ K2, const float* __restrict__ V2, int len2, int hs2,
    int P, __half* __restrict__ OutH, __half* __restrict__ OutL)
{
    constexpr int TQ = 32, TK = 32;
    int h  = blockIdx.y;
    int qb = blockIdx.x * TQ;
    int t  = threadIdx.x;
    int r  = t >> 2;
    int c4 = t & 3;
    int d0 = c4 * 16;

    __shared__ __align__(16) float Ks[TK][64];
    __shared__ __align__(16) float Vs[TK][64];

    const float* Qh = Q + (size_t)h * nq * 64;

    float qreg[16];
    #pragma unroll
    for (int i = 0; i < 16; i += 4) {
        float4 v = *(const float4*)(Qh + (size_t)(qb + r) * 64 + d0 + i);
        qreg[i + 0] = v.x * 0.125f;
        qreg[i + 1] = v.y * 0.125f;
        qreg[i + 2] = v.z * 0.125f;
        qreg[i + 3] = v.w * 0.125f;
    }

    float m = -3.0e38f, lsum = 0.0f;
    float O[16];
    #pragma unroll
    for (int i = 0; i < 16; i++) O[i] = 0.0f;

    int total = len1 + len2;
    int eff = min(total, P + qb + TQ);
    int ntk = (eff + TK - 1) / TK;
    int qi = qb + r;

    for (int kt = 0; kt < ntk; kt++) {
        int j = kt * TK + r;
        const float *kp, *vp;
        if (j < len1) {
            kp = K1 + (size_t)h * hs1 + (size_t)j * 64;
            vp = V1 + (size_t)h * hs1 + (size_t)j * 64;
        } else {
            kp = K2 + (size_t)h * hs2 + (size_t)(j - len1) * 64;
            vp = V2 + (size_t)h * hs2 + (size_t)(j - len1) * 64;
        }
        __syncthreads();
        #pragma unroll
        for (int i = 0; i < 16; i += 4) {
            *(float4*)(&Ks[r][d0 + i]) = *(const float4*)(kp + d0 + i);
            *(float4*)(&Vs[r][d0 + i]) = *(const float4*)(vp + d0 + i);
        }
        __syncthreads();

        float s[TK];
        #pragma unroll
        for (int k = 0; k < TK; k++) {
            const float4* kp4 = (const float4*)(&Ks[k][d0]);
            float a = 0.0f;
            #pragma unroll
            for (int i4 = 0; i4 < 4; i4++) {
                float4 kv = kp4[i4];
                a = fmaf(qreg[i4 * 4 + 0], kv.x, a);
                a = fmaf(qreg[i4 * 4 + 1], kv.y, a);
                a = fmaf(qreg[i4 * 4 + 2], kv.z, a);
                a = fmaf(qreg[i4 * 4 + 3], kv.w, a);
            }
            s[k] = a;
        }
        #pragma unroll
        for (int k = 0; k < TK; k++) {
            s[k] += __shfl_xor_sync(0xffffffffu, s[k], 1);
            s[k] += __shfl_xor_sync(0xffffffffu, s[k], 2);
        }
        int jg0 = kt * TK;
        #pragma unroll
        for (int k = 0; k < TK; k++) {
            int jg = jg0 + k;
            bool vis = (jg < P) || (jg - P <= qi);
            if (!vis) s[k] = -3.0e38f;
        }
        float tmax = s[0];
        #pragma unroll
        for (int k = 1; k < TK; k++) tmax = fmaxf(tmax, s[k]);
        float nm = fmaxf(m, tmax);
        float corr = __expf(m - nm);
        lsum *= corr;
        #pragma unroll
        for (int i = 0; i < 16; i++) O[i] *= corr;
        #pragma unroll
        for (int k = 0; k < TK; k++) {
            float p = __expf(s[k] - nm);
            lsum += p;
            const float4* vp4 = (const float4*)(&Vs[k][d0]);
            #pragma unroll
            for (int i4 = 0; i4 < 4; i4++) {
                float4 vv = vp4[i4];
                O[i4 * 4 + 0] = fmaf(p, vv.x, O[i4 * 4 + 0]);
                O[i4 * 4 + 1] = fmaf(p, vv.y, O[i4 * 4 + 1]);
                O[i4 * 4 + 2] = fmaf(p, vv.z, O[i4 * 4 + 2]);
                O[i4 * 4 + 3] = fmaf(p, vv.w, O[i4 * 4 + 3]);
            }
        }
        m = nm;
    }

    float inv = 1.0f / lsum;
    size_t base = (size_t)(qb + r) * 1024 + h * 64 + d0;
    #pragma unroll
    for (int i = 0; i < 16; i++) {
        float v = O[i] * inv;
        __half hh = __float2half_rn(v);
        OutH[base + i] = hh;
        OutL[base + i] = __float2half_rn(v - __half2float(hh));
    }
}

// ---------------- MLP activation -> fp16 hi/lo ----------------
__global__ void k_silu(const float* __restrict__ g, const float* __restrict__ u,
                       __half* __restrict__ oh, __half* __restrict__ ol) {
    int idx = blockIdx.x * blockDim.x + threadIdx.x;
    if (idx >= TOT * F) return;
    float x = g[idx];
    float s = x / (1.0f + expf(-x));
    float v = s * u[idx];
    __half h = __float2half_rn(v);
    oh[idx] = h;
    ol[idx] = __float2half_rn(v - __half2float(h));
}

// ---------------- host driver ----------------
extern "C" void kernel_launch(void* const* d_in, const int* in_sizes, int n_in,
                              void* d_out, int out_size) {
    (void)in_sizes; (void)n_in; (void)out_size;

    const int*   ids    = (const int*)  d_in[0];
    const float* memory = (const float*)d_in[1];
    const float* beacon = (const float*)d_in[2];
    const float* forget = (const float*)d_in[3];
    const float* embed  = (const float*)d_in[4];
    const float* ln1    = (const float*)d_in[5];
    const float* ln2    = (const float*)d_in[6];
    const float* Wsrc[12] = {
        (const float*)d_in[7],  (const float*)d_in[8],  (const float*)d_in[9],
        (const float*)d_in[10], (const float*)d_in[11], (const float*)d_in[12],
        (const float*)d_in[13], (const float*)d_in[14], (const float*)d_in[15],
        (const float*)d_in[16], (const float*)d_in[17], (const float*)d_in[18]
    }; // Wq Wk Wv Wo mWk mWv bWq bWk bWv fWq fWk fWv
    const float* Wg = (const float*)d_in[19];
    const float* Wu = (const float*)d_in[20];
    const float* Wd = (const float*)d_in[21];
    float* out = (float*)d_out;

    float* pool = nullptr;
    cudaGetSymbolAddress((void**)&pool, g_pool);
    __half* hp = nullptr;
    cudaGetSymbolAddress((void**)&hp, g_poolhf);

    float* cat  = pool + OFF_CAT;
    float* qh_f = pool + OFF_Q;
    float* qbuf_b = pool + OFF_QB;
    float* qbuf_f = pool + OFF_QF;
    float* kbuf = pool + OFF_K;
    float* vbuf = pool + OFF_V;
    float* kf   = pool + OFF_KF;
    float* vf   = pool + OFF_VF;
    float* tqkv = pool + OFF_TQKV;
    float* tsm  = pool + OFF_TSM;
    float* tg   = pool + OFF_TG;
    float* tu   = pool + OFF_TU;
    float* cosT = pool + OFF_COS;
    float* sinT = pool + OFF_SIN;

    __half* xh = hp + B_XH;  __half* xl = hp + B_XL;
    __half* ah = hp + B_AH;  __half* al = hp + B_AL;
    __half* yh = hp + B_YH;  __half* yl = hp + B_YL;
    __half* gh = hp + B_GH;  __half* gl = hp + B_GL;
    __half* meh = hp + B_MEH; __half* mel = hp + B_MEL;

    cudaFuncSetAttribute(k_hmma, cudaFuncAttributeMaxDynamicSharedMemorySize, SMEM_HM);

    k_tables<<<(1280 * 64 + 255) / 256, 256>>>(cosT, sinT);
    k_fillcat<<<(TOT * D + 255) / 256, 256>>>(cat, ids, embed, beacon, forget);

    const size_t WDD = (size_t)D * D;
    const size_t WDF = (size_t)D * F;
    const size_t WFD = (size_t)F * D;
    const size_t MDsz = (size_t)Mm * D;

    __half* wtH[15];
    for (int i = 0; i < 12; i++) wtH[i] = hp + BW_DXD + (size_t)i * 1048576;
    wtH[12] = hp + BW_WG;
    wtH[13] = hp + BW_WU;
    wtH[14] = hp + BW_WD;

    for (int l = 0; l < L; l++) {
        const float* mem_l = memory + (size_t)l * MDsz;

        // per-layer weight conversion (transpose to [N][K], single fp16 rounding)
        {
            WcArgs wa;
            int off = 0;
            for (int i = 0; i < 12; i++) {
                wa.e[i] = { Wsrc[i] + (size_t)l * WDD, wtH[i], D, D, off };
                off += (D / 32) * (D / 32);
            }
            wa.e[12] = { Wg + (size_t)l * WDF, wtH[12], D, F, off }; off += (D/32)*(F/32);
            wa.e[13] = { Wu + (size_t)l * WDF, wtH[13], D, F, off }; off += (D/32)*(F/32);
            wa.e[14] = { Wd + (size_t)l * WFD, wtH[14], F, D, off }; off += (F/32)*(D/32);
            k_wconv<<<off, 256>>>(wa);
        }
        k_split<<<(Mm * D + 255) / 256, 256>>>(mem_l, meh, mel, Mm * D);

        k_outgate<<<(Mm * D + 255) / 256, 256>>>(out + (size_t)l * MDsz, mem_l, cat);
        k_rms<<<TOT, 256>>>(cat, ln1 + (size_t)l * D, xh, xl);

        // merged: hidden QKV (z0-2, M=1024) + eight 128-row projections (z3-10)
        {
            GArgs ga = {};
            for (int z = 0; z < 3; z++) {
                ga.Ah[z] = xh; ga.Al[z] = xl;
                ga.Bh[z] = wtH[z];
                ga.C[z] = tqkv + (size_t)z * 1048576;
                ga.mRows[z] = S;
            }
            const __half* bxh = xh + (size_t)S * D;
            const __half* bxl = xl + (size_t)S * D;
            const __half* fxh = xh + (size_t)(S + Mm) * D;
            const __half* fxl = xl + (size_t)(S + Mm) * D;
            const __half* sAh[8] = { meh, meh, bxh, bxh, bxh, fxh, fxh, fxh };
            const __half* sAl[8] = { mel, mel, bxl, bxl, bxl, fxl, fxl, fxl };
            int wmap[8] = {4, 5, 6, 7, 8, 9, 10, 11}; // mWk mWv bWq bWk bWv fWq fWk fWv
            for (int z = 0; z < 8; z++) {
                ga.Ah[3 + z] = sAh[z]; ga.Al[3 + z] = sAl[z];
                ga.Bh[3 + z] = wtH[wmap[z]];
                ga.C[3 + z] = tsm + (size_t)z * 131072;
                ga.mRows[3 + z] = Mm;
            }
            k_hmma<<<dim3(8, 8, 11), 256, SMEM_HM>>>(ga, D, D, 0);
        }
        // rope + reshape
        {
            RsArgs ra;
            ra.e[0]  = { tqkv,            qh_f,   S,  1024, 0,    Mm };
            ra.e[1]  = { tqkv + 1048576,  kbuf,   S,  1280, 128,  Mm };
            ra.e[2]  = { tqkv + 2097152,  vbuf,   S,  1280, 128,  -1 };
            ra.e[3]  = { tsm,             kbuf,   Mm, 1280, 0,    0  };
            ra.e[4]  = { tsm + 131072,    vbuf,   Mm, 1280, 0,    -1 };
            ra.e[5]  = { tsm + 262144,    qbuf_b, Mm, 128,  0,    KHID };
            ra.e[6]  = { tsm + 393216,    kbuf,   Mm, 1280, KHID, KHID };
            ra.e[7]  = { tsm + 524288,    vbuf,   Mm, 1280, KHID, -1 };
            ra.e[8]  = { tsm + 655360,    qbuf_f, Mm, 128,  0,    KHID };
            ra.e[9]  = { tsm + 786432,    kf,     Mm, 128,  0,    KHID };
            ra.e[10] = { tsm + 917504,    vf,     Mm, 128,  0,    -1 };
            k_reshape<<<dim3(4096, 11), 256>>>(ra, cosT, sinT);
        }
        // attention (writes fp16 hi/lo into ah/al)
        k_attn<<<dim3(S / 32, H), 128>>>(qh_f, S,
                                         kbuf, vbuf, KHID, 1280 * 64,
                                         kf, vf, 0, 128 * 64,
                                         Mm, ah, al);
        k_attn<<<dim3(Mm / 32, H), 128>>>(qbuf_b, Mm,
                                          kbuf, vbuf, TOT, 1280 * 64,
                                          kf, vf, 0, 128 * 64,
                                          KHID, ah + (size_t)S * D, al + (size_t)S * D);
        k_attn<<<dim3(Mm / 32, H), 128>>>(qbuf_f, Mm,
                                          kbuf, vbuf, KHID, 1280 * 64,
                                          kf, vf, Mm, 128 * 64,
                                          KHID, ah + (size_t)KHID * D, al + (size_t)KHID * D);
        // Wo (+residual): M=1280, N=1024, K=1024
        {
            GArgs ga = {};
            ga.Ah[0] = ah; ga.Al[0] = al;
            ga.Bh[0] = wtH[3];
            ga.C[0] = cat;
            ga.mRows[0] = TOT;
            k_hmma<<<dim3(8, 10, 1), 256, SMEM_HM>>>(ga, D, D, 1);
        }
        k_rms<<<TOT, 256>>>(cat, ln2 + (size_t)l * D, yh, yl);
        // MLP gate & up: M=1280, N=2048, K=1024
        {
            GArgs ga = {};
            ga.Ah[0] = yh; ga.Al[0] = yl; ga.Ah[1] = yh; ga.Al[1] = yl;
            ga.Bh[0] = wtH[12];
            ga.Bh[1] = wtH[13];
            ga.C[0] = tg; ga.C[1] = tu;
            ga.mRows[0] = TOT; ga.mRows[1] = TOT;
            k_hmma<<<dim3(16, 10, 2), 256, SMEM_HM>>>(ga, F, D, 0);
        }
        k_silu<<<(TOT * F + 255) / 256, 256>>>(tg, tu, gh, gl);
        // down (+residual): M=1280, N=1024, K=2048
        {
            GArgs ga = {};
            ga.Ah[0] = gh; ga.Al[0] = gl;
            ga.Bh[0] = wtH[14];
            ga.C[0] = cat;
            ga.mRows[0] = TOT;
            k_hmma<<<dim3(8, 10, 1), 256, SMEM_HM>>>(ga, D, F, 1);
        }
    }
}

// round 8
// speedup vs baseline: 1.6074x; 1.0616x over previous
#include <cuda_runtime.h>
#include <cuda_fp16.h>
#include <math.h>

// Problem constants
constexpr int S  = 1024;
constexpr int Mm = 128;
constexpr int D  = 1024;
constexpr int H  = 16;
constexpr int HD = 64;
constexpr int F  = 2048;
constexpr int L  = 8;
constexpr int TOT = S + 2 * Mm;     // 1280
constexpr int KHID = Mm + S;        // 1152

// ---------------- f32 scratch pool ----------------
constexpr size_t OFF_CAT  = 0;                          // 1280*1024
constexpr size_t OFF_Q    = 5242880;                    // 16*1024*64
constexpr size_t OFF_QB   = 6291456;
constexpr size_t OFF_QF   = 6422528;
constexpr size_t OFF_K    = 6553600;                    // 16*1280*64
constexpr size_t OFF_V    = 7864320;
constexpr size_t OFF_KF   = 9175040;
constexpr size_t OFF_VF   = 9306112;
constexpr size_t OFF_TQKV = 9437184;                    // 3*1024*1024
constexpr size_t OFF_TSM  = 12582912;                   // 8*128*1024
constexpr size_t OFF_TG   = 13631488;                   // 1280*2048
constexpr size_t OFF_TU   = 16252928;                   // 1280*2048
constexpr size_t OFF_COS  = 18874368;
constexpr size_t OFF_SIN  = 18956288;
constexpr size_t POOL_SZ  = 19038208;
__device__ __align__(16) float g_pool[POOL_SZ];

// ---------------- fp16 scratch pool ----------------
constexpr size_t BW_DXD   = 0;                   // i-th DxD weight: i*1048576
constexpr size_t BW_WG    = 12582912;            // 2097152 each
constexpr size_t BW_WU    = 14680064;
constexpr size_t BW_WD    = 16777216;
constexpr size_t B_XH     = 18874368;            // 1280*1024
constexpr size_t B_AH     = 20185088;
constexpr size_t B_YH     = 21495808;
constexpr size_t B_GH     = 22806528;            // 1280*2048
constexpr size_t B_MEH    = 25427968;            // 128*1024
constexpr size_t BPOOL_SZ = 25559040;
__device__ __align__(16) __half g_poolhf[BPOOL_SZ];

// ---------------- rope tables ----------------
__global__ void k_tables(float* cosT, float* sinT) {
    int idx = blockIdx.x * blockDim.x + threadIdx.x;
    if (idx >= 1280 * 64) return;
    int p = idx >> 6;
    int d = idx & 63;
    int i = d & 31;
    double inv = pow(10000.0, -((double)i) / 32.0);
    double ang = (double)p * inv;
    cosT[idx] = (float)cos(ang);
    sinT[idx] = (float)sin(ang);
}

// ---------------- initial residual ----------------
__global__ void k_fillcat(float* cat, const int* __restrict__ ids,
                          const float* __restrict__ embed,
                          const float* __restrict__ beacon,
                          const float* __restrict__ forget) {
    int idx = blockIdx.x * blockDim.x + threadIdx.x;
    if (idx >= TOT * D) return;
    int row = idx >> 10;
    int d = idx & 1023;
    float v;
    if (row < S)            v = embed[(size_t)ids[row] * D + d];
    else if (row < S + Mm)  v = beacon[(size_t)(row - S) * D + d];
    else                    v = forget[(size_t)(row - S - Mm) * D + d];
    cat[idx] = v;
}

// ---------------- gated output ----------------
__global__ void k_outgate(float* __restrict__ out, const float* __restrict__ mem,
                          const float* __restrict__ cat) {
    int idx = blockIdx.x * blockDim.x + threadIdx.x;
    if (idx >= Mm * D) return;
    float bcn = cat[(size_t)S * D + idx];
    float fgt = cat[(size_t)(S + Mm) * D + idx];
    float g = 1.0f / (1.0f + expf(-fgt));
    out[idx] = mem[idx] * g + bcn * (1.0f - g);
}

// ---------------- rmsnorm -> fp16 ----------------
__global__ void k_rms(const float* __restrict__ in, const float* __restrict__ w,
                      __half* __restrict__ oh) {
    int row = blockIdx.x;
    const float* r = in + (size_t)row * D;
    float ss = 0.0f;
    for (int i = threadIdx.x; i < D; i += 256) { float v = r[i]; ss = fmaf(v, v, ss); }
    #pragma unroll
    for (int o = 16; o; o >>= 1) ss += __shfl_xor_sync(0xffffffffu, ss, o);
    __shared__ float wsum[8];
    __shared__ float sc;
    if ((threadIdx.x & 31) == 0) wsum[threadIdx.x >> 5] = ss;
    __syncthreads();
    if (threadIdx.x == 0) {
        float tot = 0.0f;
        #pragma unroll
        for (int i = 0; i < 8; i++) tot += wsum[i];
        sc = rsqrtf(tot / (float)D + 1e-5f);
    }
    __syncthreads();
    float scale = sc;
    size_t base = (size_t)row * D;
    for (int i = threadIdx.x; i < D; i += 256)
        oh[base + i] = __float2half_rn(r[i] * scale * w[i]);
}

// ---------------- weight transpose -> fp16 ----------------
struct WcEnt { const float* src; __half* dh; int K; int N; int blkOff; };
struct WcArgs { WcEnt e[15]; };

__global__ void __launch_bounds__(256) k_wconv(WcArgs wa) {
    __shared__ float ts[32][33];
    int b = blockIdx.x;
    int ei = 0;
    #pragma unroll
    for (int i = 14; i >= 1; i--) if (b >= wa.e[i].blkOff) { ei = i; break; }
    WcEnt E = wa.e[ei];
    int local = b - E.blkOff;
    int ntx = E.N >> 5;
    int tn = (local % ntx) << 5;
    int tk = (local / ntx) << 5;
    int tx = threadIdx.x & 31, ty = threadIdx.x >> 5;
    #pragma unroll
    for (int j = 0; j < 4; j++)
        ts[ty + j * 8][tx] = E.src[(size_t)(tk + ty + j * 8) * E.N + tn + tx];
    __syncthreads();
    #pragma unroll
    for (int j = 0; j < 4; j++) {
        float v = ts[tx][ty + j * 8];
        E.dh[(size_t)(tn + ty + j * 8) * E.K + tk + tx] = __float2half_rn(v);
    }
}

// ---------------- plain f32 -> fp16 ----------------
__global__ void k_split(const float* __restrict__ src, __half* __restrict__ dh, int n) {
    int i = blockIdx.x * 256 + threadIdx.x;
    if (i >= n) return;
    dh[i] = __float2half_rn(src[i]);
}

// =======================================================================
// HMMA GEMM, pure fp16: C = A@B^T (+C).  A:[M][K] fp16, B:[N][K] fp16.
// CTA tile 128x128, BK=64, 2-stage cp.async pipeline, 8 warps, 2 CTA/SM.
// smem per stage: A 16K | B 16K = 32KB; 2 stages = 64KB.
// Inner loop: 16 independent MMAs per ks (no accumulator chains).
// =======================================================================
struct GArgs {
    const __half* Ah[11];
    const __half* Bh[11];
    float* C[11];
    int mRows[11];
};

__device__ __forceinline__ void mma16816(float* c, const unsigned* a, const unsigned* b) {
    asm volatile(
        "mma.sync.aligned.m16n8k16.row.col.f32.f16.f16.f32 "
        "{%0,%1,%2,%3}, {%4,%5,%6,%7}, {%8,%9}, {%0,%1,%2,%3};"
        : "+f"(c[0]), "+f"(c[1]), "+f"(c[2]), "+f"(c[3])
        : "r"(a[0]), "r"(a[1]), "r"(a[2]), "r"(a[3]), "r"(b[0]), "r"(b[1]));
}
__device__ __forceinline__ void ldsm4(unsigned* r, unsigned addr) {
    asm volatile("ldmatrix.sync.aligned.m8n8.x4.shared.b16 {%0,%1,%2,%3}, [%4];"
                 : "=r"(r[0]), "=r"(r[1]), "=r"(r[2]), "=r"(r[3]) : "r"(addr));
}
__device__ __forceinline__ void cpasync16(unsigned saddr, const void* gptr) {
    asm volatile("cp.async.cg.shared.global [%0], [%1], 16;"
                 :: "r"(saddr), "l"(gptr) : "memory");
}
__device__ __forceinline__ void cp_commit() {
    asm volatile("cp.async.commit_group;" ::: "memory");
}
template<int NN> __device__ __forceinline__ void cp_wait() {
    asm volatile("cp.async.wait_group %0;" :: "n"(NN) : "memory");
}

constexpr int SMEM_HM = 65536;

__global__ void __launch_bounds__(256, 2) k_hmma(GArgs ga, int N, int K, int accFlag) {
    extern __shared__ __align__(128) char smraw[];
    const int z = blockIdx.z;
    const int mbase = blockIdx.y << 7;
    if (mbase >= ga.mRows[z]) return;
    const int nbase = blockIdx.x << 7;

    const __half* Ah = ga.Ah[z];
    const __half* Bh = ga.Bh[z];
    float* C = ga.C[z];

    const int t = threadIdx.x;
    const int l = t & 31;
    const int w = t >> 5;
    const int wr = w >> 2;          // 0..1 -> 64 M rows
    const int wc = w & 3;           // 0..3 -> 32 N cols
    const unsigned sb = (unsigned)__cvta_generic_to_shared(smraw);

    auto load_stage = [&](int c, int s) {
        unsigned stg = sb + (unsigned)s * 32768u;
        int k0 = c << 6;
        #pragma unroll
        for (int i = 0; i < 4; i++) {
            int id = t + i * 256;
            int row = id >> 3, kc = id & 7;
            unsigned soff = stg + (unsigned)row * 128u + (unsigned)((kc ^ (row & 7)) << 4);
            size_t ao = (size_t)(mbase + row) * K + k0 + kc * 8;
            size_t bo = (size_t)(nbase + row) * K + k0 + kc * 8;
            cpasync16(soff,          Ah + ao);
            cpasync16(soff + 16384u, Bh + bo);
        }
        cp_commit();
    };

    float acc[4][4][4];
    #pragma unroll
    for (int i = 0; i < 4; i++)
        #pragma unroll
        for (int j = 0; j < 4; j++)
            #pragma unroll
            for (int q = 0; q < 4; q++) acc[i][j][q] = 0.0f;

    const int nc = K >> 6;
    load_stage(0, 0);
    if (nc > 1) load_stage(1, 1);

    for (int c = 0; c < nc; c++) {
        if (c + 1 < nc) cp_wait<1>(); else cp_wait<0>();
        __syncthreads();
        unsigned stg = sb + (unsigned)(c & 1) * 32768u;
        #pragma unroll
        for (int ks = 0; ks < 4; ks++) {
            unsigned aH[4][4], bH[2][4];
            #pragma unroll
            for (int mt = 0; mt < 4; mt++) {
                int row = wr * 64 + mt * 16 + (l & 15);
                int chunk = ks * 2 + (l >> 4);
                unsigned off = stg + (unsigned)row * 128u + (unsigned)((chunk ^ (row & 7)) << 4);
                ldsm4(aH[mt], off);
            }
            #pragma unroll
            for (int p = 0; p < 2; p++) {
                int nrow = wc * 32 + p * 16 + ((l >> 1) & 8) + (l & 7);
                int chunk = ks * 2 + ((l >> 3) & 1);
                unsigned off = stg + 16384u + (unsigned)nrow * 128u +
                               (unsigned)((chunk ^ (nrow & 7)) << 4);
                ldsm4(bH[p], off);
            }
            #pragma unroll
            for (int mt = 0; mt < 4; mt++)
                #pragma unroll
                for (int j = 0; j < 4; j++)
                    mma16816(acc[mt][j], aH[mt], &bH[j >> 1][(j & 1) * 2]);
        }
        __syncthreads();
        if (c + 2 < nc) load_stage(c + 2, c & 1);
    }

    // epilogue
    int r0 = wr * 64 + (l >> 2);
    int c0 = wc * 32 + (l & 3) * 2;
    #pragma unroll
    for (int mt = 0; mt < 4; mt++) {
        #pragma unroll
        for (int j = 0; j < 4; j++) {
            int row = mbase + r0 + mt * 16;
            int col = nbase + c0 + j * 8;
            float2 v01 = { acc[mt][j][0], acc[mt][j][1] };
            float2 v23 = { acc[mt][j][2], acc[mt][j][3] };
            float* p0 = C + (size_t)row * N + col;
            float* p1 = C + (size_t)(row + 8) * N + col;
            if (accFlag) {
                float2 o0 = *(const float2*)p0;
                float2 o1 = *(const float2*)p1;
                v01.x += o0.x; v01.y += o0.y;
                v23.x += o1.x; v23.y += o1.y;
            }
            *(float2*)p0 = v01;
            *(float2*)p1 = v23;
        }
    }
}

// ---------------- rope + head-major reshape ----------------
struct RsOne {
    const float* src;
    float*       dst;
    int rows;
    int dstStride;
    int dstOff;
    int posBase;
};
struct RsArgs { RsOne e[11]; };

__global__ void k_reshape(RsArgs ra, const float* __restrict__ cosT,
                          const float* __restrict__ sinT) {
    RsOne a = ra.e[blockIdx.y];
    int idx = blockIdx.x * 256 + threadIdx.x;
    if (idx >= a.rows * 1024) return;
    int row = idx >> 10;
    int n = idx & 1023;
    int h = n >> 6;
    int d = n & 63;
    float v = a.src[idx];
    float o;
    if (a.posBase >= 0) {
        int pos = a.posBase + row;
        float partner = (d < 32)
            ? -a.src[(size_t)row * 1024 + h * 64 + d + 32]
            :  a.src[(size_t)row * 1024 + h * 64 + d - 32];
        o = v * cosT[pos * 64 + d] + partner * sinT[pos * 64 + d];
    } else {
        o = v;
    }
    a.dst[((size_t)h * a.dstStride + a.dstOff + row) * 64 + d] = o;
}

// ---------------- flash-style attention -> fp16 out ----------------
__global__ void __launch_bounds__(128) k_attn(
    const float* __restrict__ Q, int nq,
    const float* __restrict__ K1, const float* __restrict__ V1, int len1, int hs1,
    const float* __restrict__ K2, const float* __restrict__ V2, int len2, int hs2,
    int P, __half* __restrict__ OutH)
{
    constexpr int TQ = 32, TK = 32;
    int h  = blockIdx.y;
    int qb = blockIdx.x * TQ;
    int t  = threadIdx.x;
    int r  = t >> 2;
    int c4 = t & 3;
    int d0 = c4 * 16;

    __shared__ __align__(16) float Ks[TK][64];
    __shared__ __align__(16) float Vs[TK][64];

    const float* Qh = Q + (size_t)h * nq * 64;

    float qreg[16];
    #pragma unroll
    for (int i = 0; i < 16; i += 4) {
        float4 v = *(const float4*)(Qh + (size_t)(qb + r) * 64 + d0 + i);
        qreg[i + 0] = v.x * 0.125f;
        qreg[i + 1] = v.y * 0.125f;
        qreg[i + 2] = v.z * 0.125f;
        qreg[i + 3] = v.w * 0.125f;
    }

    float m = -3.0e38f, lsum = 0.0f;
    float O[16];
    #pragma unroll
    for (int i = 0; i < 16; i++) O[i] = 0.0f;

    int total = len1 + len2;
    int eff = min(total, P + qb + TQ);
    int ntk = (eff + TK - 1) / TK;
    int qi = qb + r;

    for (int kt = 0; kt < ntk; kt++) {
        int j = kt * TK + r;
        const float *kp, *vp;
        if (j < len1) {
            kp = K1 + (size_t)h * hs1 + (size_t)j * 64;
            vp = V1 + (size_t)h * hs1 + (size_t)j * 64;
        } else {
            kp = K2 + (size_t)h * hs2 + (size_t)(j - len1) * 64;
            vp = V2 + (size_t)h * hs2 + (size_t)(j - len1) * 64;
        }
        __syncthreads();
        #pragma unroll
        for (int i = 0; i < 16; i += 4) {
            *(float4*)(&Ks[r][d0 + i]) = *(const float4*)(kp + d0 + i);
            *(float4*)(&Vs[r][d0 + i]) = *(const float4*)(vp + d0 + i);
        }
        __syncthreads();

        float s[TK];
        #pragma unroll
        for (int k = 0; k < TK; k++) {
            const float4* kp4 = (const float4*)(&Ks[k][d0]);
            float a = 0.0f;
            #pragma unroll
            for (int i4 = 0; i4 < 4; i4++) {
                float4 kv = kp4[i4];
                a = fmaf(qreg[i4 * 4 + 0], kv.x, a);
                a = fmaf(qreg[i4 * 4 + 1], kv.y, a);
                a = fmaf(qreg[i4 * 4 + 2], kv.z, a);
                a = fmaf(qreg[i4 * 4 + 3], kv.w, a);
            }
            s[k] = a;
        }
        #pragma unroll
        for (int k = 0; k < TK; k++) {
            s[k] += __shfl_xor_sync(0xffffffffu, s[k], 1);
            s[k] += __shfl_xor_sync(0xffffffffu, s[k], 2);
        }
        int jg0 = kt * TK;
        #pragma unroll
        for (int k = 0; k < TK; k++) {
            int jg = jg0 + k;
            bool vis = (jg < P) || (jg - P <= qi);
            if (!vis) s[k] = -3.0e38f;
        }
        float tmax = s[0];
        #pragma unroll
        for (int k = 1; k < TK; k++) tmax = fmaxf(tmax, s[k]);
        float nm = fmaxf(m, tmax);
        float corr = __expf(m - nm);
        lsum *= corr;
        #pragma unroll
        for (int i = 0; i < 16; i++) O[i] *= corr;
        #pragma unroll
        for (int k = 0; k < TK; k++) {
            float p = __expf(s[k] - nm);
            lsum += p;
            const float4* vp4 = (const float4*)(&Vs[k][d0]);
            #pragma unroll
            for (int i4 = 0; i4 < 4; i4++) {
                float4 vv = vp4[i4];
                O[i4 * 4 + 0] = fmaf(p, vv.x, O[i4 * 4 + 0]);
                O[i4 * 4 + 1] = fmaf(p, vv.y, O[i4 * 4 + 1]);
                O[i4 * 4 + 2] = fmaf(p, vv.z, O[i4 * 4 + 2]);
                O[i4 * 4 + 3] = fmaf(p, vv.w, O[i4 * 4 + 3]);
            }
        }
        m = nm;
    }

    float inv = 1.0f / lsum;
    size_t base = (size_t)(qb + r) * 1024 + h * 64 + d0;
    #pragma unroll
    for (int i = 0; i < 16; i++)
        OutH[base + i] = __float2half_rn(O[i] * inv);
}

// ---------------- MLP activation -> fp16 ----------------
__global__ void k_silu(const float* __restrict__ g, const float* __restrict__ u,
                       __half* __restrict__ oh) {
    int idx = blockIdx.x * blockDim.x + threadIdx.x;
    if (idx >= TOT * F) return;
    float x = g[idx];
    float s = x / (1.0f + expf(-x));
    oh[idx] = __float2half_rn(s * u[idx]);
}

// ---------------- host driver ----------------
extern "C" void kernel_launch(void* const* d_in, const int* in_sizes, int n_in,
                              void* d_out, int out_size) {
    (void)in_sizes; (void)n_in; (void)out_size;

    const int*   ids    = (const int*)  d_in[0];
    const float* memory = (const float*)d_in[1];
    const float* beacon = (const float*)d_in[2];
    const float* forget = (const float*)d_in[3];
    const float* embed  = (const float*)d_in[4];
    const float* ln1    = (const float*)d_in[5];
    const float* ln2    = (const float*)d_in[6];
    const float* Wsrc[12] = {
        (const float*)d_in[7],  (const float*)d_in[8],  (const float*)d_in[9],
        (const float*)d_in[10], (const float*)d_in[11], (const float*)d_in[12],
        (const float*)d_in[13], (const float*)d_in[14], (const float*)d_in[15],
        (const float*)d_in[16], (const float*)d_in[17], (const float*)d_in[18]
    }; // Wq Wk Wv Wo mWk mWv bWq bWk bWv fWq fWk fWv
    const float* Wg = (const float*)d_in[19];
    const float* Wu = (const float*)d_in[20];
    const float* Wd = (const float*)d_in[21];
    float* out = (float*)d_out;

    float* pool = nullptr;
    cudaGetSymbolAddress((void**)&pool, g_pool);
    __half* hp = nullptr;
    cudaGetSymbolAddress((void**)&hp, g_poolhf);

    float* cat  = pool + OFF_CAT;
    float* qh_f = pool + OFF_Q;
    float* qbuf_b = pool + OFF_QB;
    float* qbuf_f = pool + OFF_QF;
    float* kbuf = pool + OFF_K;
    float* vbuf = pool + OFF_V;
    float* kf   = pool + OFF_KF;
    float* vf   = pool + OFF_VF;
    float* tqkv = pool + OFF_TQKV;
    float* tsm  = pool + OFF_TSM;
    float* tg   = pool + OFF_TG;
    float* tu   = pool + OFF_TU;
    float* cosT = pool + OFF_COS;
    float* sinT = pool + OFF_SIN;

    __half* xh = hp + B_XH;
    __half* ah = hp + B_AH;
    __half* yh = hp + B_YH;
    __half* gh = hp + B_GH;
    __half* meh = hp + B_MEH;

    cudaFuncSetAttribute(k_hmma, cudaFuncAttributeMaxDynamicSharedMemorySize, SMEM_HM);

    k_tables<<<(1280 * 64 + 255) / 256, 256>>>(cosT, sinT);
    k_fillcat<<<(TOT * D + 255) / 256, 256>>>(cat, ids, embed, beacon, forget);

    const size_t WDD = (size_t)D * D;
    const size_t WDF = (size_t)D * F;
    const size_t WFD = (size_t)F * D;
    const size_t MDsz = (size_t)Mm * D;

    __half* wtH[15];
    for (int i = 0; i < 12; i++) wtH[i] = hp + BW_DXD + (size_t)i * 1048576;
    wtH[12] = hp + BW_WG;
    wtH[13] = hp + BW_WU;
    wtH[14] = hp + BW_WD;

    for (int l = 0; l < L; l++) {
        const float* mem_l = memory + (size_t)l * MDsz;

        // per-layer weight conversion (transpose to [N][K], fp16)
        {
            WcArgs wa;
            int off = 0;
            for (int i = 0; i < 12; i++) {
                wa.e[i] = { Wsrc[i] + (size_t)l * WDD, wtH[i], D, D, off };
                off += (D / 32) * (D / 32);
            }
            wa.e[12] = { Wg + (size_t)l * WDF, wtH[12], D, F, off }; off += (D/32)*(F/32);
            wa.e[13] = { Wu + (size_t)l * WDF, wtH[13], D, F, off }; off += (D/32)*(F/32);
            wa.e[14] = { Wd + (size_t)l * WFD, wtH[14], F, D, off }; off += (F/32)*(D/32);
            k_wconv<<<off, 256>>>(wa);
        }
        k_split<<<(Mm * D + 255) / 256, 256>>>(mem_l, meh, Mm * D);

        k_outgate<<<(Mm * D + 255) / 256, 256>>>(out + (size_t)l * MDsz, mem_l, cat);
        k_rms<<<TOT, 256>>>(cat, ln1 + (size_t)l * D, xh);

        // hidden QKV: M=1024 (grid exactly sized)
        {
            GArgs ga = {};
            for (int z = 0; z < 3; z++) {
                ga.Ah[z] = xh;
                ga.Bh[z] = wtH[z];
                ga.C[z] = tqkv + (size_t)z * 1048576;
                ga.mRows[z] = S;
            }
            k_hmma<<<dim3(8, 8, 3), 256, SMEM_HM>>>(ga, D, D, 0);
        }
        // eight 128-row projections (grid exactly sized, no empty CTAs)
        {
            GArgs ga = {};
            const __half* bxh = xh + (size_t)S * D;
            const __half* fxh = xh + (size_t)(S + Mm) * D;
            const __half* sAh[8] = { meh, meh, bxh, bxh, bxh, fxh, fxh, fxh };
            int wmap[8] = {4, 5, 6, 7, 8, 9, 10, 11}; // mWk mWv bWq bWk bWv fWq fWk fWv
            for (int z = 0; z < 8; z++) {
                ga.Ah[z] = sAh[z];
                ga.Bh[z] = wtH[wmap[z]];
                ga.C[z] = tsm + (size_t)z * 131072;
                ga.mRows[z] = Mm;
            }
            k_hmma<<<dim3(8, 1, 8), 256, SMEM_HM>>>(ga, D, D, 0);
        }
        // rope + reshape
        {
            RsArgs ra;
            ra.e[0]  = { tqkv,            qh_f,   S,  1024, 0,    Mm };
            ra.e[1]  = { tqkv + 1048576,  kbuf,   S,  1280, 128,  Mm };
            ra.e[2]  = { tqkv + 2097152,  vbuf,   S,  1280, 128,  -1 };
            ra.e[3]  = { tsm,             kbuf,   Mm, 1280, 0,    0  };
            ra.e[4]  = { tsm + 131072,    vbuf,   Mm, 1280, 0,    -1 };
            ra.e[5]  = { tsm + 262144,    qbuf_b, Mm, 128,  0,    KHID };
            ra.e[6]  = { tsm + 393216,    kbuf,   Mm, 1280, KHID, KHID };
            ra.e[7]  = { tsm + 524288,    vbuf,   Mm, 1280, KHID, -1 };
            ra.e[8]  = { tsm + 655360,    qbuf_f, Mm, 128,  0,    KHID };
            ra.e[9]  = { tsm + 786432,    kf,     Mm, 128,  0,    KHID };
            ra.e[10] = { tsm + 917504,    vf,     Mm, 128,  0,    -1 };
            k_reshape<<<dim3(4096, 11), 256>>>(ra, cosT, sinT);
        }
        // attention (writes fp16 into ah)
        k_attn<<<dim3(S / 32, H), 128>>>(qh_f, S,
                                         kbuf, vbuf, KHID, 1280 * 64,
                                         kf, vf, 0, 128 * 64,
                                         Mm, ah);
        k_attn<<<dim3(Mm / 32, H), 128>>>(qbuf_b, Mm,
                                          kbuf, vbuf, TOT, 1280 * 64,
                                          kf, vf, 0, 128 * 64,
                                          KHID, ah + (size_t)S * D);
        k_attn<<<dim3(Mm / 32, H), 128>>>(qbuf_f, Mm,
                                          kbuf, vbuf, KHID, 1280 * 64,
                                          kf, vf, Mm, 128 * 64,
                                          KHID, ah + (size_t)KHID * D);
        // Wo (+residual): M=1280, N=1024, K=1024
        {
            GArgs ga = {};
            ga.Ah[0] = ah;
            ga.Bh[0] = wtH[3];
            ga.C[0] = cat;
            ga.mRows[0] = TOT;
            k_hmma<<<dim3(8, 10, 1), 256, SMEM_HM>>>(ga, D, D, 1);
        }
        k_rms<<<TOT, 256>>>(cat, ln2 + (size_t)l * D, yh);
        // MLP gate & up: M=1280, N=2048, K=1024
        {
            GArgs ga = {};
            ga.Ah[0] = yh; ga.Ah[1] = yh;
            ga.Bh[0] = wtH[12];
            ga.Bh[1] = wtH[13];
            ga.C[0] = tg; ga.C[1] = tu;
            ga.mRows[0] = TOT; ga.mRows[1] = TOT;
            k_hmma<<<dim3(16, 10, 2), 256, SMEM_HM>>>(ga, F, D, 0);
        }
        k_silu<<<(TOT * F + 255) / 256, 256>>>(tg, tu, gh);
        // down (+residual): M=1280, N=1024, K=2048
        {
            GArgs ga = {};
            ga.Ah[0] = gh;
            ga.Bh[0] = wtH[14];
            ga.C[0] = cat;
            ga.mRows[0] = TOT;
            k_hmma<<<dim3(8, 10, 1), 256, SMEM_HM>>>(ga, D, F, 1);
        }
    }
}